// round 15
// baseline (speedup 1.0000x reference)
#include <cuda_runtime.h>
#include <cuda_fp16.h>
#include <cstdint>
#include <cstddef>

#define SEQ    2048
#define NH     16
#define DM     1024
#define HD     64
#define HID    2730
#define HIDP   2752
#define NIN    5460
#define NINP   5504
#define ROWS   4096
#define QKVG_N 4096

// ---------------- scratch (allocation-free device globals) ----------------
__device__ float  g_x1   [ROWS*DM];
__device__ __half g_qkvg_h[(size_t)ROWS*QKVG_N];
__device__ __half g_xn_h [ROWS*DM];
__device__ __half g_xn2_h[ROWS*DM];
__device__ __half g_at_h [ROWS*DM];
__device__ __half g_hb_h [(size_t)ROWS*HIDP];
__device__ __half g_wqkvg_h[(size_t)QKVG_N*DM];
__device__ __half g_wo_h   [DM*DM];
__device__ __half g_win_h  [(size_t)NINP*DM];
__device__ __half g_wout_h [(size_t)DM*HIDP];

// ---------------- helpers ----------------
__device__ __forceinline__ void mma16(float* c, const uint32_t* a, const uint32_t* b) {
    asm volatile("mma.sync.aligned.m16n8k16.row.col.f32.f16.f16.f32 "
                 "{%0,%1,%2,%3},{%4,%5,%6,%7},{%8,%9},{%0,%1,%2,%3};\n"
                 : "+f"(c[0]), "+f"(c[1]), "+f"(c[2]), "+f"(c[3])
                 : "r"(a[0]), "r"(a[1]), "r"(a[2]), "r"(a[3]), "r"(b[0]), "r"(b[1]));
}
__device__ __forceinline__ uint32_t pack2(float x, float y) {
    __half2 h = __halves2half2(__float2half_rn(x), __float2half_rn(y));
    return *(uint32_t*)&h;
}
__device__ __forceinline__ uint32_t smem_u32(const void* p) {
    return (uint32_t)__cvta_generic_to_shared(p);
}
__device__ __forceinline__ void ldsm4(uint32_t& r0, uint32_t& r1, uint32_t& r2, uint32_t& r3,
                                      uint32_t addr) {
    asm volatile("ldmatrix.sync.aligned.m8n8.x4.shared.b16 {%0,%1,%2,%3},[%4];\n"
                 : "=r"(r0), "=r"(r1), "=r"(r2), "=r"(r3) : "r"(addr));
}
__device__ __forceinline__ void ldsm4t(uint32_t& r0, uint32_t& r1, uint32_t& r2, uint32_t& r3,
                                       uint32_t addr) {
    asm volatile("ldmatrix.sync.aligned.m8n8.x4.trans.shared.b16 {%0,%1,%2,%3},[%4];\n"
                 : "=r"(r0), "=r"(r1), "=r"(r2), "=r"(r3) : "r"(addr));
}
__device__ __forceinline__ void cpa16(uint32_t dst, const void* src) {
    asm volatile("cp.async.cg.shared.global [%0],[%1],16;\n" :: "r"(dst), "l"(src));
}

// ---------------- merged weight transpose/convert (R13-proven) + LN1 blocks ----------------
// blocks [0,13376): weight tiles (verbatim R13); [13376, 13376+ROWS): LN1 rows
#define PREP_BLKS (13376 + ROWS)

__global__ void convw_all(const float* __restrict__ wq, const float* __restrict__ wk,
                          const float* __restrict__ wv, const float* __restrict__ wg,
                          const float* __restrict__ wo, const float* __restrict__ w_in,
                          const float* __restrict__ w_out,
                          __half* __restrict__ wqk_h, __half* __restrict__ wo_h,
                          __half* __restrict__ win_h, __half* __restrict__ wout_h,
                          const float* __restrict__ x, const float* __restrict__ ln1w,
                          const float* __restrict__ ln1b, __half* __restrict__ xn_h)
{
    __shared__ float t[32][33];
    __shared__ float red[2][8];
    int bt = blockIdx.x;
    int tid = threadIdx.x;

    if (bt >= 13376) {
        // ---------------- LN1 (verbatim R13 ln_kernel body) ----------------
        int row = bt - 13376;
        const float* xr = x + (size_t)row * DM;
        float v[4], s = 0.f, q = 0.f;
#pragma unroll
        for (int i = 0; i < 4; i++) { v[i] = xr[tid + 256*i]; s += v[i]; q += v[i]*v[i]; }
#pragma unroll
        for (int off = 16; off; off >>= 1) {
            s += __shfl_xor_sync(~0u, s, off);
            q += __shfl_xor_sync(~0u, q, off);
        }
        if ((tid & 31) == 0) { red[0][tid>>5] = s; red[1][tid>>5] = q; }
        __syncthreads();
        if (tid < 32) {
            s = (tid < 8) ? red[0][tid] : 0.f;
            q = (tid < 8) ? red[1][tid] : 0.f;
#pragma unroll
            for (int off = 4; off; off >>= 1) {
                s += __shfl_xor_sync(~0u, s, off);
                q += __shfl_xor_sync(~0u, q, off);
            }
            if (tid == 0) { red[0][0] = s; red[1][0] = q; }
        }
        __syncthreads();
        s = red[0][0]; q = red[1][0];
        float mu = s * (1.f/DM);
        float rs = rsqrtf(q * (1.f/DM) - mu*mu + 1e-5f);
#pragma unroll
        for (int i = 0; i < 4; i++) {
            int c = tid + 256*i;
            xn_h[(size_t)row*DM + c] = __float2half_rn((v[i] - mu) * rs * ln1w[c] + ln1b[c]);
        }
        return;
    }

    // ---------------- weight tiles (verbatim R13) ----------------
    const float* src; __half *hiT; int sK, sN, dK, n0, k0;
    bool packed = false;
    if (bt < 4096) {
        int sub = bt >> 10, tt = bt & 1023;
        src = sub == 0 ? wq : sub == 1 ? wk : sub == 2 ? wv : wg;
        hiT = wqk_h + (size_t)sub*DM*DM;
        sK = DM; sN = DM; dK = DM; n0 = (tt & 31)*32; k0 = (tt >> 5)*32;
    } else if (bt < 5120) {
        int tt = bt - 4096;
        src = wo; hiT = wo_h;
        sK = DM; sN = DM; dK = DM; n0 = (tt & 31)*32; k0 = (tt >> 5)*32;
    } else if (bt < 10624) {
        int tt = bt - 5120;
        src = w_in; hiT = win_h; packed = true;
        sK = DM; sN = NIN; dK = DM; n0 = (tt % 172)*32; k0 = (tt / 172)*32;
    } else {
        int tt = bt - 10624;
        src = w_out; hiT = wout_h;
        sK = HID; sN = DM; dK = HIDP; n0 = (tt & 31)*32; k0 = (tt >> 5)*32;
    }
    int tx = tid & 31, ty = tid >> 5;
    int p = n0 + tx;
    int scol = packed ? ((p & 1) ? HID + (p >> 1) : (p >> 1)) : p;
    bool cok = packed ? ((p >> 1) < HID) : (scol < sN);
#pragma unroll
    for (int i = 0; i < 4; i++) {
        int k = k0 + ty + 8*i;
        float v = (k < sK && cok) ? src[(size_t)k * sN + scol] : 0.f;
        t[ty + 8*i][tx] = v;
    }
    __syncthreads();
#pragma unroll
    for (int i = 0; i < 4; i++) {
        int nl = ty + 8*i;
        hiT[(size_t)(n0 + nl) * dK + k0 + tx] = __float2half_rn(t[tx][nl]);
    }
}

// ---------------- LayerNorm -> fp16 (LN2) ----------------
__global__ void ln_kernel(const float* __restrict__ x, const float* __restrict__ w,
                          const float* __restrict__ b, __half* __restrict__ ohi)
{
    __shared__ float red[2][8];
    int row = blockIdx.x, tid = threadIdx.x;
    const float* xr = x + (size_t)row * DM;
    float v[4], s = 0.f, q = 0.f;
#pragma unroll
    for (int i = 0; i < 4; i++) { v[i] = xr[tid + 256*i]; s += v[i]; q += v[i]*v[i]; }
#pragma unroll
    for (int off = 16; off; off >>= 1) {
        s += __shfl_xor_sync(~0u, s, off);
        q += __shfl_xor_sync(~0u, q, off);
    }
    if ((tid & 31) == 0) { red[0][tid>>5] = s; red[1][tid>>5] = q; }
    __syncthreads();
    if (tid < 32) {
        s = (tid < 8) ? red[0][tid] : 0.f;
        q = (tid < 8) ? red[1][tid] : 0.f;
#pragma unroll
        for (int off = 4; off; off >>= 1) {
            s += __shfl_xor_sync(~0u, s, off);
            q += __shfl_xor_sync(~0u, q, off);
        }
        if (tid == 0) { red[0][0] = s; red[1][0] = q; }
    }
    __syncthreads();
    s = red[0][0]; q = red[1][0];
    float mu = s * (1.f/DM);
    float rs = rsqrtf(q * (1.f/DM) - mu*mu + 1e-5f);
#pragma unroll
    for (int i = 0; i < 4; i++) {
        int c = tid + 256*i;
        ohi[(size_t)row*DM + c] = __float2half_rn((v[i] - mu) * rs * w[c] + b[c]);
    }
}

// ---------------- shared GEMM mainloop: 4-stage (16KB each), 1 sync/iter ----------------
#define GP_SMEM 65536

#define ISSUE(st, kt) do {                                                   \
        uint32_t d_ = sbase + (st)*16384 + dsto;                             \
        int ko_ = (kt)*32;                                                   \
        cpa16(d_,               aS0 + ko_);                                  \
        cpa16(d_ + 4096,        aS0 + ko_ + (size_t)64*K);                   \
        cpa16(d_ + 8192,        bS0 + ko_);                                  \
        cpa16(d_ + 8192 + 4096, bS0 + ko_ + (size_t)64*K);                   \
        asm volatile("cp.async.commit_group;\n");                            \
    } while (0)

#define GEMM_MAIN(acc_)                                                          \
    int tid = threadIdx.x, lane = tid & 31, wid = tid >> 5;                      \
    int wm = wid >> 2, wn = wid & 3;                                             \
    int m0 = blockIdx.y * 128, n0 = blockIdx.x * 128;                            \
    int KT = K >> 5;                                                             \
    int cr = tid >> 2, cc = tid & 3;                                             \
    uint32_t dsto = (uint32_t)(cr*64 + ((cc ^ ((cr>>1)&3)) * 16));               \
    const __half* aS0 = Ahi + (size_t)(m0 + cr)*K + cc*8;                        \
    const __half* bS0 = Bhi + (size_t)(n0 + cr)*K + cc*8;                        \
    int l8 = lane & 7, g = lane >> 3;                                            \
    int f_rl = (g & 1)*8 + l8;                                                   \
    int f_cs = g >> 1;                                                           \
    int f_swz = (f_rl >> 1) & 3;                                                 \
    uint32_t ck[2] = { (uint32_t)(((0 + f_cs) ^ f_swz) * 16),                    \
                       (uint32_t)(((2 + f_cs) ^ f_swz) * 16) };                  \
    uint32_t aRow = (uint32_t)((wm*64 + f_rl) * 64);                             \
    uint32_t bRow = (uint32_t)((wn*32 + f_rl) * 64);                             \
    ISSUE(0, 0);                                                                 \
    ISSUE(1, 1);                                                                 \
    for (int kt = 0; kt < KT; kt++) {                                            \
        if (kt + 2 < KT) {                                                       \
            ISSUE((kt + 2) & 3, kt + 2);                                         \
            asm volatile("cp.async.wait_group 2;\n");                            \
        } else if (kt + 1 < KT) {                                                \
            asm volatile("cp.async.wait_group 1;\n");                            \
        } else {                                                                 \
            asm volatile("cp.async.wait_group 0;\n");                            \
        }                                                                        \
        __syncthreads();                                                         \
        uint32_t sb = sbase + (uint32_t)((kt & 3) * 16384);                      \
        _Pragma("unroll")                                                        \
        for (int ks = 0; ks < 2; ks++) {                                         \
            uint32_t bh[4][2], af[4][4];                                         \
            _Pragma("unroll")                                                    \
            for (int nt = 0; nt < 2; nt++) {                                     \
                uint32_t r0, r1, r2, r3;                                         \
                ldsm4(r0, r1, r2, r3, sb + 8192 + bRow + nt*1024 + ck[ks]);      \
                bh[2*nt][0] = r0; bh[2*nt+1][0] = r1;                            \
                bh[2*nt][1] = r2; bh[2*nt+1][1] = r3;                            \
            }                                                                    \
            _Pragma("unroll")                                                    \
            for (int mi = 0; mi < 4; mi++)                                       \
                ldsm4(af[mi][0], af[mi][1], af[mi][2], af[mi][3],                \
                      sb + aRow + mi*1024 + ck[ks]);                             \
            _Pragma("unroll")                                                    \
            for (int mi = 0; mi < 4; mi++)                                       \
                _Pragma("unroll")                                                \
                for (int ni = 0; ni < 4; ni++)                                   \
                    mma16(acc_[mi][ni], af[mi], bh[ni]);                         \
        }                                                                        \
    }

// generic fp32-out GEMM (+bias)(+add)
__global__ __launch_bounds__(256, 2)
void gemm_p(const __half* __restrict__ Ahi, const __half* __restrict__ Bhi,
            float* __restrict__ C, int N, int K, int ldC,
            const float* __restrict__ bias, const float* __restrict__ add)
{
    extern __shared__ __half sh[];
    uint32_t sbase = smem_u32(sh);
    float acc[4][4][4] = {};
    GEMM_MAIN(acc)
#pragma unroll
    for (int mi = 0; mi < 4; mi++) {
        int r = m0 + wm*64 + mi*16 + (lane >> 2);
#pragma unroll
        for (int ni = 0; ni < 4; ni++) {
            int cn = n0 + wn*32 + ni*8 + 2*(lane & 3);
            if (cn >= N) continue;
            float b0v = bias ? bias[cn]   : 0.f;
            float b1v = bias ? bias[cn+1] : 0.f;
            float v0 = acc[mi][ni][0] + b0v;
            float v1 = acc[mi][ni][1] + b1v;
            float v2 = acc[mi][ni][2] + b0v;
            float v3 = acc[mi][ni][3] + b1v;
            if (add) {
                v0 += add[(size_t)r*ldC + cn];     v1 += add[(size_t)r*ldC + cn + 1];
                v2 += add[(size_t)(r+8)*ldC + cn]; v3 += add[(size_t)(r+8)*ldC + cn + 1];
            }
            *(float2*)(C + (size_t)r*ldC + cn)     = make_float2(v0, v1);
            *(float2*)(C + (size_t)(r+8)*ldC + cn) = make_float2(v2, v3);
        }
    }
}

// QKVG GEMM: fp16 hi plane out
__global__ __launch_bounds__(256, 2)
void gemm_q(const __half* __restrict__ Ahi, const __half* __restrict__ Bhi,
            __half* __restrict__ Chi, int K)
{
    extern __shared__ __half sh[];
    uint32_t sbase = smem_u32(sh);
    float acc[4][4][4] = {};
    GEMM_MAIN(acc)
#pragma unroll
    for (int mi = 0; mi < 4; mi++) {
        int r = m0 + wm*64 + mi*16 + (lane >> 2);
#pragma unroll
        for (int ni = 0; ni < 4; ni++) {
            int cn = n0 + wn*32 + ni*8 + 2*(lane & 3);
#pragma unroll
            for (int hh = 0; hh < 2; hh++) {
                int rr = r + 8*hh;
                *(__half2*)(Chi + (size_t)rr*QKVG_N + cn) =
                    __halves2half2(__float2half_rn(acc[mi][ni][2*hh]),
                                   __float2half_rn(acc[mi][ni][2*hh + 1]));
            }
        }
    }
}

// FFN-in GEMM with fused swiglu: packed (a,b) pairs -> hb = a*silu(b), fp16
__global__ __launch_bounds__(256, 2)
void gemm_f(const __half* __restrict__ Ahi, const __half* __restrict__ Bhi,
            __half* __restrict__ Hb, int K, const float* __restrict__ biasIn)
{
    extern __shared__ __half sh[];
    uint32_t sbase = smem_u32(sh);
    float acc[4][4][4] = {};
    GEMM_MAIN(acc)
#pragma unroll
    for (int mi = 0; mi < 4; mi++) {
        int r = m0 + wm*64 + mi*16 + (lane >> 2);
#pragma unroll
        for (int ni = 0; ni < 4; ni++) {
            int cn = n0 + wn*32 + ni*8 + 2*(lane & 3);   // even
            int j = cn >> 1;
            bool ok = j < HID;
            float ba = ok ? biasIn[j]       : 0.f;
            float bb = ok ? biasIn[HID + j] : 0.f;
#pragma unroll
            for (int hh = 0; hh < 2; hh++) {
                int rr = r + 8*hh;
                float a  = acc[mi][ni][2*hh]     + ba;
                float bv = acc[mi][ni][2*hh + 1] + bb;
                float hv = ok ? a * bv / (1.f + __expf(-bv)) : 0.f;
                Hb[(size_t)rr*HIDP + j] = __float2half_rn(hv);
            }
        }
    }
}
#undef ISSUE

// ---------------- retention attention v9: pure fp16, 4-stage, fused gn+gate ----------------
#define ATT9_SMEM (65536 + 1024)

__global__ __launch_bounds__(256, 2)
void attn9(const __half* __restrict__ ph, __half* __restrict__ at_h)
{
    extern __shared__ char smc[];
    uint32_t sbase = smem_u32(smc);
    float* cfp = (float*)(smc + 65536);
    int tid = threadIdx.x, lane = tid & 31, w = tid >> 5;
    int bh = blockIdx.y, b = bh >> 4, h = bh & 15;
    int s0 = ((blockIdx.x * 7) & 15) * 128;
    float lg = log2f(1.f - exp2f(-5.f - (float)h));

    int dist_max = (int)(40.0f / (-lg));
    int cc0 = s0 - 63 - dist_max;
    int t_start = (cc0 <= 0) ? 0 : ((cc0 + 63) & ~63);
    int nt = (s0 + 64 - t_start)/64 + 1;

    int gq = lane >> 2, t4 = lane & 3;
    int r0 = w*16 + gq;
    int r0g = s0 + r0, r1g = r0g + 8;
    float rowf0 = exp2f((float)r0g * lg);
    float rowf1 = exp2f((float)r1g * lg);

    uint32_t qh[4][4];
    {
        const __half* qr0 = ph + (size_t)(b*SEQ + r0g)*QKVG_N + h*HD;
        const __half* qr1 = qr0 + 8*(size_t)QKVG_N;
        __half2 sc = __half2half2(__float2half_rn(0.125f));
#pragma unroll
        for (int kc = 0; kc < 4; kc++) {
            int col = kc*16 + 2*t4;
            __half2 a0 = __hmul2(*(const __half2*)(qr0 + col), sc);
            __half2 a1 = __hmul2(*(const __half2*)(qr1 + col), sc);
            __half2 a2 = __hmul2(*(const __half2*)(qr0 + col + 8), sc);
            __half2 a3 = __hmul2(*(const __half2*)(qr1 + col + 8), sc);
            qh[kc][0] = *(uint32_t*)&a0;
            qh[kc][1] = *(uint32_t*)&a1;
            qh[kc][2] = *(uint32_t*)&a2;
            qh[kc][3] = *(uint32_t*)&a3;
        }
    }

    const __half* kh = ph + DM + h*HD;
    const __half* vh = ph + 2*DM + h*HD;

#define FILL(st, t0_) do {                                                        \
        _Pragma("unroll")                                                         \
        for (int pp = 0; pp < 2; pp++) {                                          \
            int p_ = tid + 256*pp;                                                \
            int r_ = p_ >> 3, c_ = p_ & 7;                                        \
            uint32_t do_ = (uint32_t)((st)*16384 + r_*128 + ((c_ ^ (r_ & 7))<<4));\
            size_t src_ = (size_t)(b*SEQ + (t0_) + r_)*QKVG_N + c_*8;             \
            cpa16(sbase + do_,         kh + src_);                                \
            cpa16(sbase + 8192 + do_,  vh + src_);                                \
        }                                                                         \
        if (tid < 64) cfp[(st)*64 + tid] = exp2f(-(float)((t0_) + tid) * lg);     \
        asm volatile("cp.async.commit_group;\n");                                 \
    } while (0)

    FILL(0, t_start);
    if (nt > 1) FILL(1, t_start + 64);

    int l8 = lane & 7;
    int f_rl = ((lane >> 3) & 1)*8 + l8;
    int f_cs = lane >> 4;

    float oacc[8][4] = {};
    for (int it = 0; it < nt; it++) {
        int t0 = t_start + it*64;
        if (it + 2 < nt) {
            FILL((it + 2) & 3, t_start + (it + 2)*64);
            asm volatile("cp.async.wait_group 2;\n");
        } else if (it + 1 < nt) {
            asm volatile("cp.async.wait_group 1;\n");
        } else {
            asm volatile("cp.async.wait_group 0;\n");
        }
        __syncthreads();

        if (t0 <= s0 + w*16 + 15) {
            uint32_t stb = sbase + (uint32_t)((it & 3) * 16384);
            const float* cf = cfp + (it & 3)*64;
            bool full = (s0 + w*16 >= t0 + 63);   // whole warp tile unmasked

            float sacc[8][4] = {};
#pragma unroll
            for (int ks = 0; ks < 4; ks++) {
                uint32_t ca = (uint32_t)(((2*ks + f_cs) ^ l8) << 4);
#pragma unroll
                for (int nb = 0; nb < 4; nb++) {
                    uint32_t kRow = (uint32_t)((nb*16 + f_rl) * 128);
                    uint32_t h0, h1, h2, h3;
                    ldsm4(h0, h1, h2, h3, stb + kRow + ca);
                    uint32_t bh0[2] = {h0, h2}, bh1[2] = {h1, h3};
                    mma16(sacc[2*nb],   qh[ks], bh0);
                    mma16(sacc[2*nb+1], qh[ks], bh1);
                }
            }

#pragma unroll
            for (int ni = 0; ni < 8; ni++) {
                int c0 = ni*8 + 2*t4;
                float cf0 = cf[c0], cf1 = cf[c0 + 1];
                float w00, w01, w10, w11;
                if (full) {
                    w00 = rowf0*cf0; w01 = rowf0*cf1;
                    w10 = rowf1*cf0; w11 = rowf1*cf1;
                } else {
                    int c0g = t0 + c0, c1g = c0g + 1;
                    w00 = (r0g >= c0g) ? rowf0*cf0 : 0.f;
                    w01 = (r0g >= c1g) ? rowf0*cf1 : 0.f;
                    w10 = (r1g >= c0g) ? rowf1*cf0 : 0.f;
                    w11 = (r1g >= c1g) ? rowf1*cf1 : 0.f;
                }
                sacc[ni][0] *= w00; sacc[ni][1] *= w01;
                sacc[ni][2] *= w10; sacc[ni][3] *= w11;
            }

            uint32_t sh4[4][4];
#pragma unroll
            for (int t = 0; t < 4; t++) {
                sh4[t][0] = pack2(sacc[2*t][0],   sacc[2*t][1]);
                sh4[t][1] = pack2(sacc[2*t][2],   sacc[2*t][3]);
                sh4[t][2] = pack2(sacc[2*t+1][0], sacc[2*t+1][1]);
                sh4[t][3] = pack2(sacc[2*t+1][2], sacc[2*t+1][3]);
            }

#pragma unroll
            for (int ks = 0; ks < 4; ks++) {
                uint32_t vRow = (uint32_t)((ks*16 + f_rl) * 128);
#pragma unroll
                for (int nb = 0; nb < 4; nb++) {
                    uint32_t cv = (uint32_t)(((nb*2 + f_cs) ^ l8) << 4);
                    uint32_t h0, h1, h2, h3;
                    ldsm4t(h0, h1, h2, h3, stb + 8192 + vRow + cv);
                    uint32_t bh0[2] = {h0, h1}, bh1[2] = {h2, h3};
                    mma16(oacc[2*nb],   sh4[ks], bh0);
                    mma16(oacc[2*nb+1], sh4[ks], bh1);
                }
            }
        }
    }
#undef FILL

    // fused groupnorm (eps 1e-6) * silu(gate) -> at_h fp16
    float sum0 = 0.f, sq0 = 0.f, sum1 = 0.f, sq1 = 0.f;
#pragma unroll
    for (int ni = 0; ni < 8; ni++) {
        sum0 += oacc[ni][0] + oacc[ni][1];
        sq0  += oacc[ni][0]*oacc[ni][0] + oacc[ni][1]*oacc[ni][1];
        sum1 += oacc[ni][2] + oacc[ni][3];
        sq1  += oacc[ni][2]*oacc[ni][2] + oacc[ni][3]*oacc[ni][3];
    }
#pragma unroll
    for (int off = 1; off < 4; off <<= 1) {
        sum0 += __shfl_xor_sync(~0u, sum0, off);
        sq0  += __shfl_xor_sync(~0u, sq0,  off);
        sum1 += __shfl_xor_sync(~0u, sum1, off);
        sq1  += __shfl_xor_sync(~0u, sq1,  off);
    }
    float mu0 = sum0 * (1.f/64), rs0 = rsqrtf(sq0 * (1.f/64) - mu0*mu0 + 1e-6f);
    float mu1 = sum1 * (1.f/64), rs1 = rsqrtf(sq1 * (1.f/64) - mu1*mu1 + 1e-6f);

    const __half* gp0 = ph + (size_t)(b*SEQ + r0g)*QKVG_N + 3*DM + h*HD;
    const __half* gp1 = gp0 + 8*(size_t)QKVG_N;
    __half* o0 = at_h + (size_t)(b*SEQ + r0g)*DM + h*HD;
    __half* o1 = at_h + (size_t)(b*SEQ + r1g)*DM + h*HD;
#pragma unroll
    for (int ni = 0; ni < 8; ni++) {
        int d0 = ni*8 + 2*t4;
        __half2 gg0 = *(const __half2*)(gp0 + d0);
        __half2 gg1 = *(const __half2*)(gp1 + d0);
        float ga = __low2float(gg0), gb = __high2float(gg0);
        float gc = __low2float(gg1), gd = __high2float(gg1);
        ga = ga / (1.f + __expf(-ga));
        gb = gb / (1.f + __expf(-gb));
        gc = gc / (1.f + __expf(-gc));
        gd = gd / (1.f + __expf(-gd));
        float v0 = (oacc[ni][0] - mu0) * rs0 * ga;
        float v1 = (oacc[ni][1] - mu0) * rs0 * gb;
        float v2 = (oacc[ni][2] - mu1) * rs1 * gc;
        float v3 = (oacc[ni][3] - mu1) * rs1 * gd;
        *(__half2*)(o0 + d0) = __halves2half2(__float2half_rn(v0), __float2half_rn(v1));
        *(__half2*)(o1 + d0) = __halves2half2(__float2half_rn(v2), __float2half_rn(v3));
    }
}

// ---------------- launch ----------------
extern "C" void kernel_launch(void* const* d_in, const int* in_sizes, int n_in,
                              void* d_out, int out_size)
{
    const float* x     = (const float*)d_in[0];
    const float* ln1w  = (const float*)d_in[1];
    const float* ln1b  = (const float*)d_in[2];
    const float* wq    = (const float*)d_in[3];
    const float* wk    = (const float*)d_in[4];
    const float* wv    = (const float*)d_in[5];
    const float* wg    = (const float*)d_in[6];
    const float* wo    = (const float*)d_in[7];
    const float* ln2w  = (const float*)d_in[8];
    const float* ln2b  = (const float*)d_in[9];
    const float* w_in  = (const float*)d_in[10];
    const float* b_in  = (const float*)d_in[11];
    const float* w_out = (const float*)d_in[12];
    const float* b_out = (const float*)d_in[13];
    float* out = (float*)d_out;

    float *x1;
    __half *qk_h, *xn_h, *xn2_h, *at_h, *hb_h, *wqk_h, *wo_h, *win_h, *wout_h;
    cudaGetSymbolAddress((void**)&x1,    g_x1);
    cudaGetSymbolAddress((void**)&qk_h,  g_qkvg_h);
    cudaGetSymbolAddress((void**)&xn_h,  g_xn_h);
    cudaGetSymbolAddress((void**)&xn2_h, g_xn2_h);
    cudaGetSymbolAddress((void**)&at_h,  g_at_h);
    cudaGetSymbolAddress((void**)&hb_h,  g_hb_h);
    cudaGetSymbolAddress((void**)&wqk_h, g_wqkvg_h);
    cudaGetSymbolAddress((void**)&wo_h,  g_wo_h);
    cudaGetSymbolAddress((void**)&win_h, g_win_h);
    cudaGetSymbolAddress((void**)&wout_h, g_wout_h);

    cudaFuncSetAttribute(gemm_p, cudaFuncAttributeMaxDynamicSharedMemorySize, GP_SMEM);
    cudaFuncSetAttribute(gemm_q, cudaFuncAttributeMaxDynamicSharedMemorySize, GP_SMEM);
    cudaFuncSetAttribute(gemm_f, cudaFuncAttributeMaxDynamicSharedMemorySize, GP_SMEM);
    cudaFuncSetAttribute(attn9, cudaFuncAttributeMaxDynamicSharedMemorySize, ATT9_SMEM);

    // 1. fused weight prep (R13-proven path) + LN1
    convw_all<<<PREP_BLKS, 256>>>(wq, wk, wv, wg, wo, w_in, w_out,
                                  wqk_h, wo_h, win_h, wout_h,
                                  x, ln1w, ln1b, xn_h);
    // 2. fused QKVG -> fp16 plane
    gemm_q<<<dim3(QKVG_N/128, ROWS/128), 256, GP_SMEM>>>(xn_h, wqk_h, qk_h, DM);
    // 3. retention attention + fused groupnorm/gate -> at_h fp16
    attn9<<<dim3(SEQ/128, 2*NH), 256, ATT9_SMEM>>>(qk_h, at_h);
    // 4. output projection + residual
    gemm_p<<<dim3(DM/128, ROWS/128), 256, GP_SMEM>>>(at_h, wo_h,
        x1, DM, DM, DM, nullptr, x);
    // 5. LN2 -> fp16
    ln_kernel<<<ROWS, 256>>>(x1, ln2w, ln2b, xn2_h);
    // 6. FFN in + fused swiglu -> hb fp16
    gemm_f<<<dim3(NINP/128, ROWS/128), 256, GP_SMEM>>>(xn2_h, win_h, hb_h, DM, b_in);
    // 7. FFN out + bias + residual
    gemm_p<<<dim3(DM/128, ROWS/128), 256, GP_SMEM>>>(hb_h, wout_h,
        out, DM, HIDP, DM, b_out, x1);
}